// round 6
// baseline (speedup 1.0000x reference)
#include <cuda_runtime.h>
#include <cuda_bf16.h>
#include <mma.h>
#include <math.h>

using namespace nvcuda;

#define NUM_USERS 100000
#define NUM_ITEMS 50000
#define N_NODES   150000
#define N_EDGES   2400000
#define EMB       64
#define BATCH     4096
#define TAU       0.2f
#define SSL_LAMBDA 0.1f
#define REG_LAMBDA 1e-4f

#define NVEC4      (N_NODES * EMB / 4)    // 2,400,000 == N_EDGES
#define NROWS_PAD  150016                 // 586 * 256
#define SCAN_BLKS  586

// ---------------- device scratch (static, zero-initialized at load) ----------
__device__ __align__(16) __nv_bfloat16 g_b0[N_NODES * EMB];
__device__ __align__(16) __nv_bfloat16 g_b1[N_NODES * EMB];
__device__ __align__(16) __nv_bfloat16 g_b2[N_NODES * EMB];
__device__ __align__(16) __nv_bfloat16 g_b3[N_NODES * EMB];
__device__ __align__(16) __nv_bfloat16 g_unb[BATCH * EMB];
__device__ __align__(16) __nv_bfloat16 g_pnb[BATCH * EMB];
__device__ float g_rowsum[BATCH];   // zeroed at end of k_logsum each run
__device__ float g_scal[4];         // zeroed at end of k_final each run
__device__ int   g_ctr;             // zeroed at end of k_final each run

// CSR scratch
__device__ int   g_deg[NROWS_PAD];  // zeroed inside k_gemm each run
__device__ int   g_rowptr[NROWS_PAD];
__device__ int   g_fill[NROWS_PAD];
__device__ __align__(8) int2 g_epack[N_EDGES];   // {col, val bits}

// ---------------- combo: b0 = bf16(concat(uw,iw)) AND degree histogram -------
__global__ __launch_bounds__(256) void k_combo(const float* __restrict__ uw,
                                               const float* __restrict__ iw,
                                               const int*   __restrict__ rows) {
    int i = blockIdx.x * blockDim.x + threadIdx.x;
    const int UV = NUM_USERS * EMB / 4;
    float4 v = (i < UV) ? ((const float4*)uw)[i] : ((const float4*)iw)[i - UV];
    __nv_bfloat162 lo = __floats2bfloat162_rn(v.x, v.y);
    __nv_bfloat162 hi = __floats2bfloat162_rn(v.z, v.w);
    uint2 pk;
    pk.x = *reinterpret_cast<unsigned*>(&lo);
    pk.y = *reinterpret_cast<unsigned*>(&hi);
    ((uint2*)g_b0)[i] = pk;
    atomicAdd(&g_deg[rows[i]], 1);
}

// ---------------- CSR offsets: block scan + atomic base ----------------------
__global__ __launch_bounds__(256) void k_csr() {
    int i = blockIdx.x * 256 + threadIdx.x;
    int v = g_deg[i];
    int lane = threadIdx.x & 31, wid = threadIdx.x >> 5;
    int x = v;
    #pragma unroll
    for (int o = 1; o < 32; o <<= 1) {
        int y = __shfl_up_sync(0xffffffffu, x, o);
        if (lane >= o) x += y;
    }
    __shared__ int wsum[8];
    __shared__ int base_sh;
    if (lane == 31) wsum[wid] = x;
    __syncthreads();
    if (threadIdx.x < 8) {
        int t = wsum[threadIdx.x];
        #pragma unroll
        for (int o = 1; o < 8; o <<= 1) {
            int y = __shfl_up_sync(0xffu, t, o);
            if (threadIdx.x >= o) t += y;
        }
        wsum[threadIdx.x] = t;
    }
    __syncthreads();
    int incl = x + (wid ? wsum[wid - 1] : 0);
    if (threadIdx.x == 255) base_sh = atomicAdd(&g_ctr, incl);
    __syncthreads();
    int start = base_sh + incl - v;
    g_rowptr[i] = start;
    g_fill[i]   = start;
}

__global__ __launch_bounds__(256) void k_scatter(const int*   __restrict__ rows,
                                                 const int*   __restrict__ cols,
                                                 const float* __restrict__ vals) {
    int e = blockIdx.x * blockDim.x + threadIdx.x;
    if (e >= N_EDGES) return;
    int r = rows[e];
    int p = atomicAdd(&g_fill[r], 1);
    int2 pk;
    pk.x = cols[e];
    pk.y = __float_as_int(vals[e]);
    g_epack[p] = pk;
}

// ---------------- bf16 CSR SpMM: warp/row, 4 neighbors per slot --------------
// 4 groups of 8 lanes; each lane owns 8 dims (16B LDG.128 per gather),
// bf16->fp32 via 1-op shift/mask unpack, fp32 accumulate.
__global__ __launch_bounds__(256) void k_spmm(const __nv_bfloat16* __restrict__ b_in,
                                              __nv_bfloat16*       __restrict__ b_out) {
    int w = (blockIdx.x * 256 + threadIdx.x) >> 5;
    int lane = threadIdx.x & 31;
    if (w >= N_NODES) return;
    int grp = lane >> 3;             // neighbor slot 0..3
    int sub = lane & 7;              // dims sub*8 .. sub*8+7
    int start = g_rowptr[w];
    int deg   = g_deg[w];
    const int2* ep = g_epack + start;

    float acc[8];
    #pragma unroll
    for (int k = 0; k < 8; k++) acc[k] = 0.0f;

    #define DOEDGE(E) { \
        float v = __int_as_float((E).y); \
        uint4 raw = *(const uint4*)(b_in + (unsigned)(E).x * EMB + sub * 8); \
        acc[0] += v * __uint_as_float(raw.x << 16); \
        acc[1] += v * __uint_as_float(raw.x & 0xffff0000u); \
        acc[2] += v * __uint_as_float(raw.y << 16); \
        acc[3] += v * __uint_as_float(raw.y & 0xffff0000u); \
        acc[4] += v * __uint_as_float(raw.z << 16); \
        acc[5] += v * __uint_as_float(raw.z & 0xffff0000u); \
        acc[6] += v * __uint_as_float(raw.w << 16); \
        acc[7] += v * __uint_as_float(raw.w & 0xffff0000u); }

    int j = 0;
    for (; j + 8 <= deg; j += 8) {               // 2 gathers in flight
        int2 e0 = ep[j + grp];
        int2 e1 = ep[j + 4 + grp];
        DOEDGE(e0);
        DOEDGE(e1);
    }
    for (; j + 4 <= deg; j += 4) {
        int2 e = ep[j + grp];
        DOEDGE(e);
    }
    if (j + grp < deg) {
        int2 e = ep[j + grp];
        DOEDGE(e);
    }
    #undef DOEDGE

    // reduce the 4 neighbor groups
    #pragma unroll
    for (int k = 0; k < 8; k++) {
        acc[k] += __shfl_xor_sync(0xffffffffu, acc[k], 8);
        acc[k] += __shfl_xor_sync(0xffffffffu, acc[k], 16);
    }
    if (grp == 0) {
        __nv_bfloat162 p0 = __floats2bfloat162_rn(acc[0], acc[1]);
        __nv_bfloat162 p1 = __floats2bfloat162_rn(acc[2], acc[3]);
        __nv_bfloat162 p2 = __floats2bfloat162_rn(acc[4], acc[5]);
        __nv_bfloat162 p3 = __floats2bfloat162_rn(acc[6], acc[7]);
        uint4 pk;
        pk.x = *reinterpret_cast<unsigned*>(&p0);
        pk.y = *reinterpret_cast<unsigned*>(&p1);
        pk.z = *reinterpret_cast<unsigned*>(&p2);
        pk.w = *reinterpret_cast<unsigned*>(&p3);
        *(uint4*)(b_out + (size_t)w * EMB + sub * 8) = pk;
    }
}

// ---------------- gather: fp32 e0 + bf16 layers; BPR/reg/diag; bf16 un/pn ----
__global__ __launch_bounds__(256) void k_gather(const int* __restrict__ user,
                                                const int* __restrict__ pos,
                                                const int* __restrict__ neg,
                                                const float* __restrict__ uw,
                                                const float* __restrict__ iw) {
    int gw   = (blockIdx.x * blockDim.x + threadIdx.x) >> 5;
    int lane = threadIdx.x & 31;
    if (gw >= BATCH) return;
    int ui = user[gw], pi = pos[gw], ni = neg[gw];
    size_t uoff = (size_t)ui * EMB + lane * 2;
    size_t poff = (size_t)pi * EMB + lane * 2;
    size_t noff = (size_t)ni * EMB + lane * 2;
    size_t uno  = (size_t)ui * EMB + lane * 2;
    size_t pno  = (size_t)(NUM_USERS + pi) * EMB + lane * 2;
    size_t nno  = (size_t)(NUM_USERS + ni) * EMB + lane * 2;

    #define B2F(tab, off) __bfloat1622float2(*(const __nv_bfloat162*)((tab) + (off)))
    #define SUMALL(f32p, f32off, boff, dst) { \
        float2 base = *(const float2*)((f32p) + (f32off)); \
        float2 a1 = B2F(g_b1, boff), a2 = B2F(g_b2, boff), a3 = B2F(g_b3, boff); \
        dst.x = 0.25f * (base.x + a1.x + a2.x + a3.x); \
        dst.y = 0.25f * (base.y + a1.y + a2.y + a3.y); }
    float2 u, p, n;
    SUMALL(uw, uoff, uno, u);
    SUMALL(iw, poff, pno, p);
    SUMALL(iw, noff, nno, n);
    #undef SUMALL
    #undef B2F

    float s_up = u.x * p.x + u.y * p.y;
    float s_un = u.x * n.x + u.y * n.y;
    float s_uu = u.x * u.x + u.y * u.y;
    float s_pp = p.x * p.x + p.y * p.y;
    float s_nn = n.x * n.x + n.y * n.y;
    #pragma unroll
    for (int o = 16; o; o >>= 1) {
        s_up += __shfl_xor_sync(0xffffffffu, s_up, o);
        s_un += __shfl_xor_sync(0xffffffffu, s_un, o);
        s_uu += __shfl_xor_sync(0xffffffffu, s_uu, o);
        s_pp += __shfl_xor_sync(0xffffffffu, s_pp, o);
        s_nn += __shfl_xor_sync(0xffffffffu, s_nn, o);
    }
    float iu = rsqrtf(s_uu);
    float ip = rsqrtf(s_pp);
    *(__nv_bfloat162*)(g_unb + (size_t)gw * EMB + lane * 2) = __floats2bfloat162_rn(u.x * iu, u.y * iu);
    *(__nv_bfloat162*)(g_pnb + (size_t)gw * EMB + lane * 2) = __floats2bfloat162_rn(p.x * ip, p.y * ip);
    if (lane == 0) {
        float d  = s_up - s_un;
        float sp = fmaxf(-d, 0.0f) + log1pf(expf(-fabsf(d)));  // softplus(-d)
        atomicAdd(&g_scal[0], sp);
        atomicAdd(&g_scal[1], s_uu + s_pp + s_nn);
        float diag = s_up * iu * ip * (1.0f / TAU);             // exact pos logit
        atomicAdd(&g_scal[2], -diag);
    }
}

// ---------------- WMMA bf16 GEMM (64x64 tile) fused with exp row-sum ---------
#define LDT 80
__global__ __launch_bounds__(256) void k_gemm() {
    __shared__ __nv_bfloat16 Asm[64 * LDT];
    __shared__ __nv_bfloat16 Bsm[64 * LDT];
    __shared__ float         Csm[64 * 64];
    int bi = blockIdx.y * 64, bj = blockIdx.x * 64;
    int tid = threadIdx.x;

    // housekeeping: re-zero g_deg for the next run (first 586 blocks)
    int bid = blockIdx.y * 64 + blockIdx.x;
    if (bid < SCAN_BLKS) g_deg[bid * 256 + tid] = 0;

    #pragma unroll
    for (int pass = 0; pass < 2; pass++) {
        int row = pass * 32 + (tid >> 3);
        int col = (tid & 7) * 8;
        *(uint4*)(Asm + row * LDT + col) = *(const uint4*)(g_unb + (size_t)(bi + row) * EMB + col);
        *(uint4*)(Bsm + row * LDT + col) = *(const uint4*)(g_pnb + (size_t)(bj + row) * EMB + col);
    }
    __syncthreads();

    int wid = tid >> 5;
    int frow = wid >> 1;
    int fcol0 = (wid & 1) * 2;
    wmma::fragment<wmma::accumulator, 16, 16, 16, float> acc0, acc1;
    wmma::fill_fragment(acc0, 0.0f);
    wmma::fill_fragment(acc1, 0.0f);
    #pragma unroll
    for (int kk = 0; kk < 64; kk += 16) {
        wmma::fragment<wmma::matrix_a, 16, 16, 16, __nv_bfloat16, wmma::row_major> af;
        wmma::fragment<wmma::matrix_b, 16, 16, 16, __nv_bfloat16, wmma::col_major> bf0, bf1;
        wmma::load_matrix_sync(af, Asm + frow * 16 * LDT + kk, LDT);
        wmma::load_matrix_sync(bf0, Bsm + (fcol0 + 0) * 16 * LDT + kk, LDT);
        wmma::load_matrix_sync(bf1, Bsm + (fcol0 + 1) * 16 * LDT + kk, LDT);
        wmma::mma_sync(acc0, af, bf0, acc0);
        wmma::mma_sync(acc1, af, bf1, acc1);
    }
    wmma::store_matrix_sync(Csm + frow * 16 * 64 + (fcol0 + 0) * 16, acc0, 64, wmma::mem_row_major);
    wmma::store_matrix_sync(Csm + frow * 16 * 64 + (fcol0 + 1) * 16, acc1, 64, wmma::mem_row_major);
    __syncthreads();

    const float invTau = 1.0f / TAU;
    int row = tid >> 2;
    int seg = (tid & 3) * 16;
    const float* Crow = Csm + row * 64 + seg;
    float s = 0.0f;
    #pragma unroll
    for (int q = 0; q < 16; q++) s += __expf(Crow[q] * invTau);
    s += __shfl_xor_sync(0xffffffffu, s, 1);
    s += __shfl_xor_sync(0xffffffffu, s, 2);
    if ((tid & 3) == 0) atomicAdd(&g_rowsum[bi + row], s);
}

// ---------------- sum of log(rowsum); zero rowsum for next run ---------------
__global__ __launch_bounds__(256) void k_logsum() {
    int i = blockIdx.x * blockDim.x + threadIdx.x;
    float v = logf(g_rowsum[i]);
    g_rowsum[i] = 0.0f;
    #pragma unroll
    for (int o = 16; o; o >>= 1) v += __shfl_xor_sync(0xffffffffu, v, o);
    __shared__ float ws[8];
    int lane = threadIdx.x & 31, wid = threadIdx.x >> 5;
    if (lane == 0) ws[wid] = v;
    __syncthreads();
    if (threadIdx.x == 0) {
        float s = 0.f;
        #pragma unroll
        for (int k = 0; k < 8; k++) s += ws[k];
        atomicAdd(&g_scal[2], s);
    }
}

// ---------------- finalize; reset accumulators for next run ------------------
__global__ void k_final(float* out) {
    float bpr = g_scal[0] / BATCH;
    float reg = 0.5f * g_scal[1] / BATCH * REG_LAMBDA;
    float na  = g_scal[2] / BATCH * SSL_LAMBDA;
    out[0] = bpr + reg + na;
    g_scal[0] = 0.f; g_scal[1] = 0.f; g_scal[2] = 0.f; g_scal[3] = 0.f;
    g_ctr = 0;
}

// ---------------- host -------------------------------------------------------
extern "C" void kernel_launch(void* const* d_in, const int* in_sizes, int n_in,
                              void* d_out, int out_size) {
    const int*   user  = (const int*)d_in[0];
    const int*   pos   = (const int*)d_in[1];
    const int*   neg   = (const int*)d_in[2];
    const int*   arow  = (const int*)d_in[3];
    const int*   acol  = (const int*)d_in[4];
    const float* aval  = (const float*)d_in[5];
    const float* uw    = (const float*)d_in[6];
    const float* iw    = (const float*)d_in[7];
    float* out = (float*)d_out;

    __nv_bfloat16 *b0, *b1, *b2, *b3;
    cudaGetSymbolAddress((void**)&b0, g_b0);
    cudaGetSymbolAddress((void**)&b1, g_b1);
    cudaGetSymbolAddress((void**)&b2, g_b2);
    cudaGetSymbolAddress((void**)&b3, g_b3);

    const int TB = 256;
    const int edge_blocks = N_EDGES / TB;                  // 9375
    const int row_blocks  = (N_NODES * 32 + TB - 1) / TB;  // 18750

    k_combo<<<edge_blocks, TB>>>(uw, iw, arow);            // 1
    k_csr<<<SCAN_BLKS, TB>>>();                            // 2
    k_scatter<<<edge_blocks, TB>>>(arow, acol, aval);      // 3
    k_spmm<<<row_blocks, TB>>>(b0, b1);                    // 4
    k_spmm<<<row_blocks, TB>>>(b1, b2);                    // 5
    k_spmm<<<row_blocks, TB>>>(b2, b3);                    // 6
    k_gather<<<(BATCH * 32) / TB, TB>>>(user, pos, neg, uw, iw);   // 7
    k_gemm<<<dim3(BATCH / 64, BATCH / 64), TB>>>();        // 8
    k_logsum<<<BATCH / TB, TB>>>();                        // 9
    k_final<<<1, 1>>>(out);                                // 10
}

// round 7
// speedup vs baseline: 1.1669x; 1.1669x over previous
#include <cuda_runtime.h>
#include <cuda_bf16.h>
#include <mma.h>
#include <math.h>

using namespace nvcuda;

#define NUM_USERS 100000
#define NUM_ITEMS 50000
#define N_NODES   150000
#define N_EDGES   2400000
#define EMB       64
#define BATCH     4096
#define TAU       0.2f
#define SSL_LAMBDA 0.1f
#define REG_LAMBDA 1e-4f

#define NVEC4      (N_NODES * EMB / 4)    // 2,400,000 == N_EDGES
#define NROWS_PAD  150016                 // 586 * 256
#define SCAN_BLKS  586

// ---------------- device scratch (static, zero-initialized at load) ----------
__device__ __align__(16) __nv_bfloat16 g_b0[N_NODES * EMB];
__device__ __align__(16) __nv_bfloat16 g_b1[N_NODES * EMB];
__device__ __align__(16) __nv_bfloat16 g_b2[N_NODES * EMB];
__device__ __align__(16) __nv_bfloat16 g_b3[N_NODES * EMB];
__device__ __align__(16) __nv_bfloat16 g_unb[BATCH * EMB];
__device__ __align__(16) __nv_bfloat16 g_pnb[BATCH * EMB];
__device__ float g_rowsum[BATCH];   // zeroed at end of k_logsum each run
__device__ float g_scal[4];         // zeroed at end of k_final each run
__device__ int   g_ctr;             // zeroed at end of k_final each run

// CSR scratch
__device__ int   g_deg[NROWS_PAD];  // zeroed inside k_gemm each run
__device__ int   g_rowptr[NROWS_PAD];
__device__ int   g_fill[NROWS_PAD];
__device__ __align__(8) int2 g_epack[N_EDGES];   // {col, val bits}

// ---------------- combo: b0 = bf16(concat(uw,iw)) AND degree histogram -------
__global__ __launch_bounds__(256) void k_combo(const float* __restrict__ uw,
                                               const float* __restrict__ iw,
                                               const int*   __restrict__ rows) {
    int i = blockIdx.x * blockDim.x + threadIdx.x;
    const int UV = NUM_USERS * EMB / 4;
    float4 v = (i < UV) ? ((const float4*)uw)[i] : ((const float4*)iw)[i - UV];
    __nv_bfloat162 lo = __floats2bfloat162_rn(v.x, v.y);
    __nv_bfloat162 hi = __floats2bfloat162_rn(v.z, v.w);
    uint2 pk;
    pk.x = *reinterpret_cast<unsigned*>(&lo);
    pk.y = *reinterpret_cast<unsigned*>(&hi);
    ((uint2*)g_b0)[i] = pk;
    atomicAdd(&g_deg[rows[i]], 1);
}

// ---------------- CSR offsets: block scan + atomic base ----------------------
__global__ __launch_bounds__(256) void k_csr() {
    int i = blockIdx.x * 256 + threadIdx.x;
    int v = g_deg[i];
    int lane = threadIdx.x & 31, wid = threadIdx.x >> 5;
    int x = v;
    #pragma unroll
    for (int o = 1; o < 32; o <<= 1) {
        int y = __shfl_up_sync(0xffffffffu, x, o);
        if (lane >= o) x += y;
    }
    __shared__ int wsum[8];
    __shared__ int base_sh;
    if (lane == 31) wsum[wid] = x;
    __syncthreads();
    if (threadIdx.x < 8) {
        int t = wsum[threadIdx.x];
        #pragma unroll
        for (int o = 1; o < 8; o <<= 1) {
            int y = __shfl_up_sync(0xffu, t, o);
            if (threadIdx.x >= o) t += y;
        }
        wsum[threadIdx.x] = t;
    }
    __syncthreads();
    int incl = x + (wid ? wsum[wid - 1] : 0);
    if (threadIdx.x == 255) base_sh = atomicAdd(&g_ctr, incl);
    __syncthreads();
    int start = base_sh + incl - v;
    g_rowptr[i] = start;
    g_fill[i]   = start;
}

__global__ __launch_bounds__(256) void k_scatter(const int*   __restrict__ rows,
                                                 const int*   __restrict__ cols,
                                                 const float* __restrict__ vals) {
    int e = blockIdx.x * blockDim.x + threadIdx.x;
    if (e >= N_EDGES) return;
    int r = rows[e];
    int p = atomicAdd(&g_fill[r], 1);
    int2 pk;
    pk.x = cols[e];
    pk.y = __float_as_int(vals[e]);
    g_epack[p] = pk;
}

// ---------------- bf16 CSR SpMM: warp/row, half-warp per neighbor ------------
// 2 groups of 16 lanes (one 128B line per edge gather); 4 indices prefetched
// per 8-edge chunk so 4 gathers are in flight; 1-op shift/mask bf16 unpack.
__global__ __launch_bounds__(256) void k_spmm(const __nv_bfloat16* __restrict__ b_in,
                                              __nv_bfloat16*       __restrict__ b_out) {
    int w = (blockIdx.x * 256 + threadIdx.x) >> 5;
    int lane = threadIdx.x & 31;
    if (w >= N_NODES) return;
    int half = lane >> 4;            // 0 or 1
    int sub  = lane & 15;            // dims sub*4 .. sub*4+3
    int start = g_rowptr[w];
    int deg   = g_deg[w];
    const int2* ep = g_epack + start;

    float4 acc = make_float4(0.f, 0.f, 0.f, 0.f);

    #define UNFMA(RAW, V) { \
        acc.x += (V) * __uint_as_float((RAW).x << 16); \
        acc.y += (V) * __uint_as_float((RAW).x & 0xffff0000u); \
        acc.z += (V) * __uint_as_float((RAW).y << 16); \
        acc.w += (V) * __uint_as_float((RAW).y & 0xffff0000u); }

    int j = 0;
    for (; j + 8 <= deg; j += 8) {
        // prefetch 4 edge records for this half
        int2 e0 = ep[j + 0 + half];
        int2 e1 = ep[j + 2 + half];
        int2 e2 = ep[j + 4 + half];
        int2 e3 = ep[j + 6 + half];
        // 4 independent gathers in flight
        uint2 r0 = *(const uint2*)(b_in + (unsigned)e0.x * EMB + sub * 4);
        uint2 r1 = *(const uint2*)(b_in + (unsigned)e1.x * EMB + sub * 4);
        uint2 r2 = *(const uint2*)(b_in + (unsigned)e2.x * EMB + sub * 4);
        uint2 r3 = *(const uint2*)(b_in + (unsigned)e3.x * EMB + sub * 4);
        UNFMA(r0, __int_as_float(e0.y));
        UNFMA(r1, __int_as_float(e1.y));
        UNFMA(r2, __int_as_float(e2.y));
        UNFMA(r3, __int_as_float(e3.y));
    }
    for (; j < deg; j += 2) {
        int jj = j + half;
        if (jj < deg) {
            int2 e = ep[jj];
            uint2 r = *(const uint2*)(b_in + (unsigned)e.x * EMB + sub * 4);
            UNFMA(r, __int_as_float(e.y));
        }
    }
    #undef UNFMA

    // combine the two halves
    acc.x += __shfl_xor_sync(0xffffffffu, acc.x, 16);
    acc.y += __shfl_xor_sync(0xffffffffu, acc.y, 16);
    acc.z += __shfl_xor_sync(0xffffffffu, acc.z, 16);
    acc.w += __shfl_xor_sync(0xffffffffu, acc.w, 16);
    if (half == 0) {
        __nv_bfloat162 lo = __floats2bfloat162_rn(acc.x, acc.y);
        __nv_bfloat162 hi = __floats2bfloat162_rn(acc.z, acc.w);
        uint2 pk;
        pk.x = *reinterpret_cast<unsigned*>(&lo);
        pk.y = *reinterpret_cast<unsigned*>(&hi);
        *(uint2*)(b_out + (size_t)w * EMB + sub * 4) = pk;
    }
}

// ---------------- gather: fp32 e0 + bf16 layers; BPR/reg/diag; bf16 un/pn ----
__global__ __launch_bounds__(256) void k_gather(const int* __restrict__ user,
                                                const int* __restrict__ pos,
                                                const int* __restrict__ neg,
                                                const float* __restrict__ uw,
                                                const float* __restrict__ iw) {
    int gw   = (blockIdx.x * blockDim.x + threadIdx.x) >> 5;
    int lane = threadIdx.x & 31;
    if (gw >= BATCH) return;
    int ui = user[gw], pi = pos[gw], ni = neg[gw];
    size_t uoff = (size_t)ui * EMB + lane * 2;
    size_t poff = (size_t)pi * EMB + lane * 2;
    size_t noff = (size_t)ni * EMB + lane * 2;
    size_t uno  = (size_t)ui * EMB + lane * 2;
    size_t pno  = (size_t)(NUM_USERS + pi) * EMB + lane * 2;
    size_t nno  = (size_t)(NUM_USERS + ni) * EMB + lane * 2;

    #define B2F(tab, off) __bfloat1622float2(*(const __nv_bfloat162*)((tab) + (off)))
    #define SUMALL(f32p, f32off, boff, dst) { \
        float2 base = *(const float2*)((f32p) + (f32off)); \
        float2 a1 = B2F(g_b1, boff), a2 = B2F(g_b2, boff), a3 = B2F(g_b3, boff); \
        dst.x = 0.25f * (base.x + a1.x + a2.x + a3.x); \
        dst.y = 0.25f * (base.y + a1.y + a2.y + a3.y); }
    float2 u, p, n;
    SUMALL(uw, uoff, uno, u);
    SUMALL(iw, poff, pno, p);
    SUMALL(iw, noff, nno, n);
    #undef SUMALL
    #undef B2F

    float s_up = u.x * p.x + u.y * p.y;
    float s_un = u.x * n.x + u.y * n.y;
    float s_uu = u.x * u.x + u.y * u.y;
    float s_pp = p.x * p.x + p.y * p.y;
    float s_nn = n.x * n.x + n.y * n.y;
    #pragma unroll
    for (int o = 16; o; o >>= 1) {
        s_up += __shfl_xor_sync(0xffffffffu, s_up, o);
        s_un += __shfl_xor_sync(0xffffffffu, s_un, o);
        s_uu += __shfl_xor_sync(0xffffffffu, s_uu, o);
        s_pp += __shfl_xor_sync(0xffffffffu, s_pp, o);
        s_nn += __shfl_xor_sync(0xffffffffu, s_nn, o);
    }
    float iu = rsqrtf(s_uu);
    float ip = rsqrtf(s_pp);
    *(__nv_bfloat162*)(g_unb + (size_t)gw * EMB + lane * 2) = __floats2bfloat162_rn(u.x * iu, u.y * iu);
    *(__nv_bfloat162*)(g_pnb + (size_t)gw * EMB + lane * 2) = __floats2bfloat162_rn(p.x * ip, p.y * ip);
    if (lane == 0) {
        float d  = s_up - s_un;
        float sp = fmaxf(-d, 0.0f) + log1pf(expf(-fabsf(d)));  // softplus(-d)
        atomicAdd(&g_scal[0], sp);
        atomicAdd(&g_scal[1], s_uu + s_pp + s_nn);
        float diag = s_up * iu * ip * (1.0f / TAU);             // exact pos logit
        atomicAdd(&g_scal[2], -diag);
    }
}

// ---------------- WMMA bf16 GEMM (64x64 tile) fused with exp row-sum ---------
#define LDT 80
__global__ __launch_bounds__(256) void k_gemm() {
    __shared__ __nv_bfloat16 Asm[64 * LDT];
    __shared__ __nv_bfloat16 Bsm[64 * LDT];
    __shared__ float         Csm[64 * 64];
    int bi = blockIdx.y * 64, bj = blockIdx.x * 64;
    int tid = threadIdx.x;

    // housekeeping: re-zero g_deg for the next run (first 586 blocks)
    int bid = blockIdx.y * 64 + blockIdx.x;
    if (bid < SCAN_BLKS) g_deg[bid * 256 + tid] = 0;

    #pragma unroll
    for (int pass = 0; pass < 2; pass++) {
        int row = pass * 32 + (tid >> 3);
        int col = (tid & 7) * 8;
        *(uint4*)(Asm + row * LDT + col) = *(const uint4*)(g_unb + (size_t)(bi + row) * EMB + col);
        *(uint4*)(Bsm + row * LDT + col) = *(const uint4*)(g_pnb + (size_t)(bj + row) * EMB + col);
    }
    __syncthreads();

    int wid = tid >> 5;
    int frow = wid >> 1;
    int fcol0 = (wid & 1) * 2;
    wmma::fragment<wmma::accumulator, 16, 16, 16, float> acc0, acc1;
    wmma::fill_fragment(acc0, 0.0f);
    wmma::fill_fragment(acc1, 0.0f);
    #pragma unroll
    for (int kk = 0; kk < 64; kk += 16) {
        wmma::fragment<wmma::matrix_a, 16, 16, 16, __nv_bfloat16, wmma::row_major> af;
        wmma::fragment<wmma::matrix_b, 16, 16, 16, __nv_bfloat16, wmma::col_major> bf0, bf1;
        wmma::load_matrix_sync(af, Asm + frow * 16 * LDT + kk, LDT);
        wmma::load_matrix_sync(bf0, Bsm + (fcol0 + 0) * 16 * LDT + kk, LDT);
        wmma::load_matrix_sync(bf1, Bsm + (fcol0 + 1) * 16 * LDT + kk, LDT);
        wmma::mma_sync(acc0, af, bf0, acc0);
        wmma::mma_sync(acc1, af, bf1, acc1);
    }
    wmma::store_matrix_sync(Csm + frow * 16 * 64 + (fcol0 + 0) * 16, acc0, 64, wmma::mem_row_major);
    wmma::store_matrix_sync(Csm + frow * 16 * 64 + (fcol0 + 1) * 16, acc1, 64, wmma::mem_row_major);
    __syncthreads();

    const float invTau = 1.0f / TAU;
    int row = tid >> 2;
    int seg = (tid & 3) * 16;
    const float* Crow = Csm + row * 64 + seg;
    float s = 0.0f;
    #pragma unroll
    for (int q = 0; q < 16; q++) s += __expf(Crow[q] * invTau);
    s += __shfl_xor_sync(0xffffffffu, s, 1);
    s += __shfl_xor_sync(0xffffffffu, s, 2);
    if ((tid & 3) == 0) atomicAdd(&g_rowsum[bi + row], s);
}

// ---------------- sum of log(rowsum); zero rowsum for next run ---------------
__global__ __launch_bounds__(256) void k_logsum() {
    int i = blockIdx.x * blockDim.x + threadIdx.x;
    float v = logf(g_rowsum[i]);
    g_rowsum[i] = 0.0f;
    #pragma unroll
    for (int o = 16; o; o >>= 1) v += __shfl_xor_sync(0xffffffffu, v, o);
    __shared__ float ws[8];
    int lane = threadIdx.x & 31, wid = threadIdx.x >> 5;
    if (lane == 0) ws[wid] = v;
    __syncthreads();
    if (threadIdx.x == 0) {
        float s = 0.f;
        #pragma unroll
        for (int k = 0; k < 8; k++) s += ws[k];
        atomicAdd(&g_scal[2], s);
    }
}

// ---------------- finalize; reset accumulators for next run ------------------
__global__ void k_final(float* out) {
    float bpr = g_scal[0] / BATCH;
    float reg = 0.5f * g_scal[1] / BATCH * REG_LAMBDA;
    float na  = g_scal[2] / BATCH * SSL_LAMBDA;
    out[0] = bpr + reg + na;
    g_scal[0] = 0.f; g_scal[1] = 0.f; g_scal[2] = 0.f; g_scal[3] = 0.f;
    g_ctr = 0;
}

// ---------------- host -------------------------------------------------------
extern "C" void kernel_launch(void* const* d_in, const int* in_sizes, int n_in,
                              void* d_out, int out_size) {
    const int*   user  = (const int*)d_in[0];
    const int*   pos   = (const int*)d_in[1];
    const int*   neg   = (const int*)d_in[2];
    const int*   arow  = (const int*)d_in[3];
    const int*   acol  = (const int*)d_in[4];
    const float* aval  = (const float*)d_in[5];
    const float* uw    = (const float*)d_in[6];
    const float* iw    = (const float*)d_in[7];
    float* out = (float*)d_out;

    __nv_bfloat16 *b0, *b1, *b2, *b3;
    cudaGetSymbolAddress((void**)&b0, g_b0);
    cudaGetSymbolAddress((void**)&b1, g_b1);
    cudaGetSymbolAddress((void**)&b2, g_b2);
    cudaGetSymbolAddress((void**)&b3, g_b3);

    const int TB = 256;
    const int edge_blocks = N_EDGES / TB;                  // 9375
    const int row_blocks  = (N_NODES * 32 + TB - 1) / TB;  // 18750

    k_combo<<<edge_blocks, TB>>>(uw, iw, arow);            // 1
    k_csr<<<SCAN_BLKS, TB>>>();                            // 2
    k_scatter<<<edge_blocks, TB>>>(arow, acol, aval);      // 3
    k_spmm<<<row_blocks, TB>>>(b0, b1);                    // 4
    k_spmm<<<row_blocks, TB>>>(b1, b2);                    // 5
    k_spmm<<<row_blocks, TB>>>(b2, b3);                    // 6
    k_gather<<<(BATCH * 32) / TB, TB>>>(user, pos, neg, uw, iw);   // 7
    k_gemm<<<dim3(BATCH / 64, BATCH / 64), TB>>>();        // 8
    k_logsum<<<BATCH / TB, TB>>>();                        // 9
    k_final<<<1, 1>>>(out);                                // 10
}

// round 8
// speedup vs baseline: 1.2155x; 1.0417x over previous
#include <cuda_runtime.h>
#include <cuda_bf16.h>
#include <mma.h>
#include <math.h>

using namespace nvcuda;

#define NUM_USERS 100000
#define NUM_ITEMS 50000
#define N_NODES   150000
#define N_EDGES   2400000
#define EMB       64
#define BATCH     4096
#define TAU       0.2f
#define SSL_LAMBDA 0.1f
#define REG_LAMBDA 1e-4f

#define NVEC4      (N_NODES * EMB / 4)    // 2,400,000 == N_EDGES
#define NROWS_PAD  150016                 // 586 * 256
#define SCAN_BLKS  586

// ---------------- device scratch (static, zero-initialized at load) ----------
__device__ __align__(16) __nv_bfloat16 g_b0[N_NODES * EMB];
__device__ __align__(16) __nv_bfloat16 g_b1[N_NODES * EMB];
__device__ __align__(16) __nv_bfloat16 g_b2[N_NODES * EMB];
__device__ __align__(16) __nv_bfloat16 g_b3[N_NODES * EMB];
__device__ __align__(16) __nv_bfloat16 g_unb[BATCH * EMB];
__device__ __align__(16) __nv_bfloat16 g_pnb[BATCH * EMB];
__device__ float g_rowsum[BATCH];   // zeroed at end of k_logsum each run
__device__ float g_scal[4];         // zeroed at end of k_final each run
__device__ int   g_ctr;             // zeroed at end of k_final each run

// CSR scratch
__device__ int   g_deg[NROWS_PAD];  // zeroed inside k_gemm each run
__device__ int   g_rowptr[NROWS_PAD];
__device__ int   g_fill[NROWS_PAD];
__device__ __align__(8) int2 g_epack[N_EDGES];   // {col, bf16x2{v,v}}

// ---------------- combo: b0 = bf16(concat(uw,iw)) AND degree histogram -------
__global__ __launch_bounds__(256) void k_combo(const float* __restrict__ uw,
                                               const float* __restrict__ iw,
                                               const int*   __restrict__ rows) {
    int i = blockIdx.x * blockDim.x + threadIdx.x;
    const int UV = NUM_USERS * EMB / 4;
    float4 v = (i < UV) ? ((const float4*)uw)[i] : ((const float4*)iw)[i - UV];
    __nv_bfloat162 lo = __floats2bfloat162_rn(v.x, v.y);
    __nv_bfloat162 hi = __floats2bfloat162_rn(v.z, v.w);
    uint2 pk;
    pk.x = *reinterpret_cast<unsigned*>(&lo);
    pk.y = *reinterpret_cast<unsigned*>(&hi);
    ((uint2*)g_b0)[i] = pk;
    atomicAdd(&g_deg[rows[i]], 1);
}

// ---------------- CSR offsets: block scan + atomic base ----------------------
__global__ __launch_bounds__(256) void k_csr() {
    int i = blockIdx.x * 256 + threadIdx.x;
    int v = g_deg[i];
    int lane = threadIdx.x & 31, wid = threadIdx.x >> 5;
    int x = v;
    #pragma unroll
    for (int o = 1; o < 32; o <<= 1) {
        int y = __shfl_up_sync(0xffffffffu, x, o);
        if (lane >= o) x += y;
    }
    __shared__ int wsum[8];
    __shared__ int base_sh;
    if (lane == 31) wsum[wid] = x;
    __syncthreads();
    if (threadIdx.x < 8) {
        int t = wsum[threadIdx.x];
        #pragma unroll
        for (int o = 1; o < 8; o <<= 1) {
            int y = __shfl_up_sync(0xffu, t, o);
            if (threadIdx.x >= o) t += y;
        }
        wsum[threadIdx.x] = t;
    }
    __syncthreads();
    int incl = x + (wid ? wsum[wid - 1] : 0);
    if (threadIdx.x == 255) base_sh = atomicAdd(&g_ctr, incl);
    __syncthreads();
    int start = base_sh + incl - v;
    g_rowptr[i] = start;
    g_fill[i]   = start;
}

__global__ __launch_bounds__(256) void k_scatter(const int*   __restrict__ rows,
                                                 const int*   __restrict__ cols,
                                                 const float* __restrict__ vals) {
    int e = blockIdx.x * blockDim.x + threadIdx.x;
    if (e >= N_EDGES) return;
    int r = rows[e];
    int p = atomicAdd(&g_fill[r], 1);
    __nv_bfloat162 vv = __bfloat162bfloat162(__float2bfloat16(vals[e]));  // {v,v}
    int2 pk;
    pk.x = cols[e];
    pk.y = *reinterpret_cast<int*>(&vv);
    g_epack[p] = pk;
}

// ---------------- bf16 CSR SpMM: warp/row, half-warp per neighbor, HFMA2 -----
// 2 groups of 16 lanes (one 128B line per edge gather); edge value stored as
// pre-duplicated bf16x2, so the inner loop is gather + 2 HFMA2 per edge.
__global__ __launch_bounds__(256) void k_spmm(const __nv_bfloat16* __restrict__ b_in,
                                              __nv_bfloat16*       __restrict__ b_out) {
    int w = (blockIdx.x * 256 + threadIdx.x) >> 5;
    int lane = threadIdx.x & 31;
    if (w >= N_NODES) return;
    int half = lane >> 4;            // 0 or 1
    int sub  = lane & 15;            // dims sub*4 .. sub*4+3
    int start = g_rowptr[w];
    int deg   = g_deg[w];
    const int2* ep = g_epack + start;

    __nv_bfloat162 acc0 = __floats2bfloat162_rn(0.f, 0.f);
    __nv_bfloat162 acc1 = acc0;

    #define DOE(E, R) { \
        __nv_bfloat162 v2 = *reinterpret_cast<const __nv_bfloat162*>(&(E).y); \
        acc0 = __hfma2(*reinterpret_cast<__nv_bfloat162*>(&(R).x), v2, acc0); \
        acc1 = __hfma2(*reinterpret_cast<__nv_bfloat162*>(&(R).y), v2, acc1); }

    int j = 0;
    for (; j + 8 <= deg; j += 8) {
        int2 e0 = ep[j + 0 + half];
        int2 e1 = ep[j + 2 + half];
        int2 e2 = ep[j + 4 + half];
        int2 e3 = ep[j + 6 + half];
        uint2 r0 = *(const uint2*)(b_in + (unsigned)e0.x * EMB + sub * 4);
        uint2 r1 = *(const uint2*)(b_in + (unsigned)e1.x * EMB + sub * 4);
        uint2 r2 = *(const uint2*)(b_in + (unsigned)e2.x * EMB + sub * 4);
        uint2 r3 = *(const uint2*)(b_in + (unsigned)e3.x * EMB + sub * 4);
        DOE(e0, r0);
        DOE(e1, r1);
        DOE(e2, r2);
        DOE(e3, r3);
    }
    for (; j < deg; j += 2) {
        int jj = j + half;
        if (jj < deg) {
            int2 e = ep[jj];
            uint2 r = *(const uint2*)(b_in + (unsigned)e.x * EMB + sub * 4);
            DOE(e, r);
        }
    }
    #undef DOE

    // combine the two halves in fp32
    float2 f0 = __bfloat1622float2(acc0);
    float2 f1 = __bfloat1622float2(acc1);
    f0.x += __shfl_xor_sync(0xffffffffu, f0.x, 16);
    f0.y += __shfl_xor_sync(0xffffffffu, f0.y, 16);
    f1.x += __shfl_xor_sync(0xffffffffu, f1.x, 16);
    f1.y += __shfl_xor_sync(0xffffffffu, f1.y, 16);
    if (half == 0) {
        __nv_bfloat162 lo = __floats2bfloat162_rn(f0.x, f0.y);
        __nv_bfloat162 hi = __floats2bfloat162_rn(f1.x, f1.y);
        uint2 pk;
        pk.x = *reinterpret_cast<unsigned*>(&lo);
        pk.y = *reinterpret_cast<unsigned*>(&hi);
        *(uint2*)(b_out + (size_t)w * EMB + sub * 4) = pk;
    }
}

// ---------------- gather: fp32 e0 + bf16 layers; BPR/reg/diag; bf16 un/pn ----
__global__ __launch_bounds__(256) void k_gather(const int* __restrict__ user,
                                                const int* __restrict__ pos,
                                                const int* __restrict__ neg,
                                                const float* __restrict__ uw,
                                                const float* __restrict__ iw) {
    int gw   = (blockIdx.x * blockDim.x + threadIdx.x) >> 5;
    int lane = threadIdx.x & 31;
    if (gw >= BATCH) return;
    int ui = user[gw], pi = pos[gw], ni = neg[gw];
    size_t uoff = (size_t)ui * EMB + lane * 2;
    size_t poff = (size_t)pi * EMB + lane * 2;
    size_t noff = (size_t)ni * EMB + lane * 2;
    size_t uno  = (size_t)ui * EMB + lane * 2;
    size_t pno  = (size_t)(NUM_USERS + pi) * EMB + lane * 2;
    size_t nno  = (size_t)(NUM_USERS + ni) * EMB + lane * 2;

    #define B2F(tab, off) __bfloat1622float2(*(const __nv_bfloat162*)((tab) + (off)))
    #define SUMALL(f32p, f32off, boff, dst) { \
        float2 base = *(const float2*)((f32p) + (f32off)); \
        float2 a1 = B2F(g_b1, boff), a2 = B2F(g_b2, boff), a3 = B2F(g_b3, boff); \
        dst.x = 0.25f * (base.x + a1.x + a2.x + a3.x); \
        dst.y = 0.25f * (base.y + a1.y + a2.y + a3.y); }
    float2 u, p, n;
    SUMALL(uw, uoff, uno, u);
    SUMALL(iw, poff, pno, p);
    SUMALL(iw, noff, nno, n);
    #undef SUMALL
    #undef B2F

    float s_up = u.x * p.x + u.y * p.y;
    float s_un = u.x * n.x + u.y * n.y;
    float s_uu = u.x * u.x + u.y * u.y;
    float s_pp = p.x * p.x + p.y * p.y;
    float s_nn = n.x * n.x + n.y * n.y;
    #pragma unroll
    for (int o = 16; o; o >>= 1) {
        s_up += __shfl_xor_sync(0xffffffffu, s_up, o);
        s_un += __shfl_xor_sync(0xffffffffu, s_un, o);
        s_uu += __shfl_xor_sync(0xffffffffu, s_uu, o);
        s_pp += __shfl_xor_sync(0xffffffffu, s_pp, o);
        s_nn += __shfl_xor_sync(0xffffffffu, s_nn, o);
    }
    float iu = rsqrtf(s_uu);
    float ip = rsqrtf(s_pp);
    *(__nv_bfloat162*)(g_unb + (size_t)gw * EMB + lane * 2) = __floats2bfloat162_rn(u.x * iu, u.y * iu);
    *(__nv_bfloat162*)(g_pnb + (size_t)gw * EMB + lane * 2) = __floats2bfloat162_rn(p.x * ip, p.y * ip);
    if (lane == 0) {
        float d  = s_up - s_un;
        float sp = fmaxf(-d, 0.0f) + log1pf(expf(-fabsf(d)));  // softplus(-d)
        atomicAdd(&g_scal[0], sp);
        atomicAdd(&g_scal[1], s_uu + s_pp + s_nn);
        float diag = s_up * iu * ip * (1.0f / TAU);             // exact pos logit
        atomicAdd(&g_scal[2], -diag);
    }
}

// ---------------- WMMA bf16 GEMM (64x64 tile) fused with exp row-sum ---------
#define LDT 80
__global__ __launch_bounds__(256) void k_gemm() {
    __shared__ __nv_bfloat16 Asm[64 * LDT];
    __shared__ __nv_bfloat16 Bsm[64 * LDT];
    __shared__ float         Csm[64 * 64];
    int bi = blockIdx.y * 64, bj = blockIdx.x * 64;
    int tid = threadIdx.x;

    // housekeeping: re-zero g_deg for the next run (first 586 blocks)
    int bid = blockIdx.y * 64 + blockIdx.x;
    if (bid < SCAN_BLKS) g_deg[bid * 256 + tid] = 0;

    #pragma unroll
    for (int pass = 0; pass < 2; pass++) {
        int row = pass * 32 + (tid >> 3);
        int col = (tid & 7) * 8;
        *(uint4*)(Asm + row * LDT + col) = *(const uint4*)(g_unb + (size_t)(bi + row) * EMB + col);
        *(uint4*)(Bsm + row * LDT + col) = *(const uint4*)(g_pnb + (size_t)(bj + row) * EMB + col);
    }
    __syncthreads();

    int wid = tid >> 5;
    int frow = wid >> 1;
    int fcol0 = (wid & 1) * 2;
    wmma::fragment<wmma::accumulator, 16, 16, 16, float> acc0, acc1;
    wmma::fill_fragment(acc0, 0.0f);
    wmma::fill_fragment(acc1, 0.0f);
    #pragma unroll
    for (int kk = 0; kk < 64; kk += 16) {
        wmma::fragment<wmma::matrix_a, 16, 16, 16, __nv_bfloat16, wmma::row_major> af;
        wmma::fragment<wmma::matrix_b, 16, 16, 16, __nv_bfloat16, wmma::col_major> bf0, bf1;
        wmma::load_matrix_sync(af, Asm + frow * 16 * LDT + kk, LDT);
        wmma::load_matrix_sync(bf0, Bsm + (fcol0 + 0) * 16 * LDT + kk, LDT);
        wmma::load_matrix_sync(bf1, Bsm + (fcol0 + 1) * 16 * LDT + kk, LDT);
        wmma::mma_sync(acc0, af, bf0, acc0);
        wmma::mma_sync(acc1, af, bf1, acc1);
    }
    wmma::store_matrix_sync(Csm + frow * 16 * 64 + (fcol0 + 0) * 16, acc0, 64, wmma::mem_row_major);
    wmma::store_matrix_sync(Csm + frow * 16 * 64 + (fcol0 + 1) * 16, acc1, 64, wmma::mem_row_major);
    __syncthreads();

    const float invTau = 1.0f / TAU;
    int row = tid >> 2;
    int seg = (tid & 3) * 16;
    const float* Crow = Csm + row * 64 + seg;
    float s = 0.0f;
    #pragma unroll
    for (int q = 0; q < 16; q++) s += __expf(Crow[q] * invTau);
    s += __shfl_xor_sync(0xffffffffu, s, 1);
    s += __shfl_xor_sync(0xffffffffu, s, 2);
    if ((tid & 3) == 0) atomicAdd(&g_rowsum[bi + row], s);
}

// ---------------- sum of log(rowsum); zero rowsum for next run ---------------
__global__ __launch_bounds__(256) void k_logsum() {
    int i = blockIdx.x * blockDim.x + threadIdx.x;
    float v = logf(g_rowsum[i]);
    g_rowsum[i] = 0.0f;
    #pragma unroll
    for (int o = 16; o; o >>= 1) v += __shfl_xor_sync(0xffffffffu, v, o);
    __shared__ float ws[8];
    int lane = threadIdx.x & 31, wid = threadIdx.x >> 5;
    if (lane == 0) ws[wid] = v;
    __syncthreads();
    if (threadIdx.x == 0) {
        float s = 0.f;
        #pragma unroll
        for (int k = 0; k < 8; k++) s += ws[k];
        atomicAdd(&g_scal[2], s);
    }
}

// ---------------- finalize; reset accumulators for next run ------------------
__global__ void k_final(float* out) {
    float bpr = g_scal[0] / BATCH;
    float reg = 0.5f * g_scal[1] / BATCH * REG_LAMBDA;
    float na  = g_scal[2] / BATCH * SSL_LAMBDA;
    out[0] = bpr + reg + na;
    g_scal[0] = 0.f; g_scal[1] = 0.f; g_scal[2] = 0.f; g_scal[3] = 0.f;
    g_ctr = 0;
}

// ---------------- host -------------------------------------------------------
extern "C" void kernel_launch(void* const* d_in, const int* in_sizes, int n_in,
                              void* d_out, int out_size) {
    const int*   user  = (const int*)d_in[0];
    const int*   pos   = (const int*)d_in[1];
    const int*   neg   = (const int*)d_in[2];
    const int*   arow  = (const int*)d_in[3];
    const int*   acol  = (const int*)d_in[4];
    const float* aval  = (const float*)d_in[5];
    const float* uw    = (const float*)d_in[6];
    const float* iw    = (const float*)d_in[7];
    float* out = (float*)d_out;

    __nv_bfloat16 *b0, *b1, *b2, *b3;
    cudaGetSymbolAddress((void**)&b0, g_b0);
    cudaGetSymbolAddress((void**)&b1, g_b1);
    cudaGetSymbolAddress((void**)&b2, g_b2);
    cudaGetSymbolAddress((void**)&b3, g_b3);

    const int TB = 256;
    const int edge_blocks = N_EDGES / TB;                  // 9375
    const int row_blocks  = (N_NODES * 32 + TB - 1) / TB;  // 18750

    k_combo<<<edge_blocks, TB>>>(uw, iw, arow);            // 1
    k_csr<<<SCAN_BLKS, TB>>>();                            // 2
    k_scatter<<<edge_blocks, TB>>>(arow, acol, aval);      // 3
    k_spmm<<<row_blocks, TB>>>(b0, b1);                    // 4
    k_spmm<<<row_blocks, TB>>>(b1, b2);                    // 5
    k_spmm<<<row_blocks, TB>>>(b2, b3);                    // 6
    k_gather<<<(BATCH * 32) / TB, TB>>>(user, pos, neg, uw, iw);   // 7
    k_gemm<<<dim3(BATCH / 64, BATCH / 64), TB>>>();        // 8
    k_logsum<<<BATCH / TB, TB>>>();                        // 9
    k_final<<<1, 1>>>(out);                                // 10
}